// round 13
// baseline (speedup 1.0000x reference)
#include <cuda_runtime.h>
#include <cstddef>

#define LCH   4096
#define BATCH 4096
#define NTHR  1024
#define NSEG  128          // segments of 32, handled by threads 0..127 in phase A

struct Pots { float pd, po, pA0, pA1, pB0, pB1; };

__device__ __forceinline__ Pots make_pots(const float* jp, const float* bp) {
    Pots P;
    float j = jp[0], b0 = bp[0], b1 = bp[1];
    P.pd  = expf( 0.25f * j);
    P.po  = expf(-0.25f * j);
    P.pA0 = expf(-0.5f * b0);  P.pA1 = expf(0.5f * b0);
    P.pB0 = expf(-0.5f * b1);  P.pB1 = expf(0.5f * b1);
    return P;
}

// (max,*) 2x2 matrix product: C = A x B.  layout x=m00 y=m01 z=m10 w=m11
__device__ __forceinline__ float4 mm(float4 A, float4 B) {
    return make_float4(
        fmaxf(A.x * B.x, A.y * B.z), fmaxf(A.x * B.y, A.y * B.w),
        fmaxf(A.z * B.x, A.w * B.z), fmaxf(A.z * B.y, A.w * B.w));
}

__device__ __forceinline__ float4 shflup4(float4 v, int d) {
    v.x = __shfl_up_sync(0xffffffffu, v.x, d);
    v.y = __shfl_up_sync(0xffffffffu, v.y, d);
    v.z = __shfl_up_sync(0xffffffffu, v.z, d);
    v.w = __shfl_up_sync(0xffffffffu, v.w, d);
    return v;
}
__device__ __forceinline__ float4 shfldn4(float4 v, int d) {
    v.x = __shfl_down_sync(0xffffffffu, v.x, d);
    v.y = __shfl_down_sync(0xffffffffu, v.y, d);
    v.z = __shfl_down_sync(0xffffffffu, v.z, d);
    v.w = __shfl_down_sync(0xffffffffu, v.w, d);
    return v;
}

// ---------------------------------------------------------------------------
// One 1024-thread block per row.
// Phase A (threads 0-127): segment matrices + PP/SS chunk products to smem,
//   dual warp scan, per-segment boundary messages to smem.
// Phase B (all 1024): thread t owns positions [4t,4t+4); recovers f/b from
//   PP/SS + boundary msgs; writes beliefs DIRECTLY to gmem, fully coalesced.
// ---------------------------------------------------------------------------
__global__ void __launch_bounds__(NTHR, 2)
fused(const float* __restrict__ jp, const float* __restrict__ bp,
      const int* __restrict__ obs, float* __restrict__ out)
{
    __shared__ float4 ppB[1024];            // 16 KB chunk prefix products
    __shared__ float4 ssB[1024];            // 16 KB chunk suffix products
    __shared__ float2 fB[NSEG], gB[NSEG];   // 2 KB boundary messages
    __shared__ unsigned char smNib[1024];   // 1 KB obs nibbles
    __shared__ float4 lutP[16], lutQ[16];
    __shared__ float4 wTotP[4], wTotQ[4];

    const int t = threadIdx.x, b = blockIdx.x;
    const Pots pt = make_pots(jp, bp);

    // ---- obs: one int4 per thread; keep own nibble in register ----
    const int4* row4 = reinterpret_cast<const int4*>(obs + (size_t)b * LCH);
    int4 v = row4[t];
    const unsigned nib = (v.x & 1) | ((v.y & 1) << 1) | ((v.z & 1) << 2) | ((v.w & 1) << 3);
    smNib[t] = (unsigned char)nib;

    // ---- 4-bit LUTs of 4-step transfer matrices ----
    if (t >= 1024 - 16) {                   // last warp builds LUTs (t-1008 -> 0..15)
        int m = t - (1024 - 16);
        float p00 = 1.f, p01 = 0.f, p10 = 0.f, p11 = 1.f;
        float q00 = 1.f, q01 = 0.f, q10 = 0.f, q11 = 1.f;
#pragma unroll
        for (int i = 0; i < 4; i++) {
            int   o  = (m >> i) & 1;
            float f0 = o ? pt.pB0 : pt.pA0;
            float f1 = o ? pt.pB1 : pt.pA1;
            float x0 = f0 * p00, x1 = f1 * p10, y0 = f0 * p01, y1 = f1 * p11;
            p00 = fmaxf(x0 * pt.pd, x1 * pt.po); p10 = fmaxf(x0 * pt.po, x1 * pt.pd);
            p01 = fmaxf(y0 * pt.pd, y1 * pt.po); p11 = fmaxf(y0 * pt.po, y1 * pt.pd);
            float a = f0 * fmaxf(q00 * pt.pd, q01 * pt.po);
            float c = f1 * fmaxf(q00 * pt.po, q01 * pt.pd);
            float d = f0 * fmaxf(q10 * pt.pd, q11 * pt.po);
            float e = f1 * fmaxf(q10 * pt.po, q11 * pt.pd);
            q00 = a; q01 = c; q10 = d; q11 = e;
        }
        lutP[m] = make_float4(p00, p01, p10, p11);
        lutQ[m] = make_float4(q00, q01, q10, q11);
    }
    __syncthreads();

    // ---- Phase A: threads 0-127, one segment each ----
    if (t < NSEG) {
        const int lane = t & 31, warp = t >> 5;

        uint2 nb = reinterpret_cast<const uint2*>(smNib)[t];
        unsigned lo   = nb.x | (nb.x >> 4);
        unsigned lo16 = (lo & 0xFFu) | ((lo >> 8) & 0xFF00u);
        unsigned hi   = nb.y | (nb.y >> 4);
        unsigned hi16 = (hi & 0xFFu) | ((hi >> 8) & 0xFF00u);
        const unsigned bits = lo16 | (hi16 << 16);

        // compose, saving chunk prefix (PP) and suffix (SS) products.
        // swizzled index: chunk c of segment t lives at 8t + (c ^ (t&7)).
        float4 P = make_float4(1.f, 0.f, 0.f, 1.f);
#pragma unroll
        for (int c = 0; c < 8; c++) {
            ppB[(t << 3) | (c ^ (t & 7))] = P;
            P = mm(lutP[(bits >> (4 * c)) & 15u], P);
        }
        float4 Q = make_float4(1.f, 0.f, 0.f, 1.f);
#pragma unroll
        for (int c = 7; c >= 0; c--) {
            ssB[(t << 3) | (c ^ (t & 7))] = Q;
            Q = mm(lutQ[(bits >> (4 * c)) & 15u], Q);
        }

        // dual warp scan
        float4 sp = P;
#pragma unroll
        for (int d = 1; d < 32; d <<= 1) {
            float4 o = shflup4(sp, d);
            if (lane >= d) sp = mm(sp, o);
        }
        if (lane == 31) wTotP[warp] = sp;

        float4 sq = Q;
#pragma unroll
        for (int d = 1; d < 32; d <<= 1) {
            float4 o = shfldn4(sq, d);
            if (lane + d < 32) sq = mm(sq, o);
        }
        if (lane == 0) wTotQ[warp] = sq;
        __syncwarp();
        // cross-warp totals need all 4 warps: block-sync below covers it
        // (threads >=128 are just waiting there anyway)
        __syncthreads();

        float4 prefP = make_float4(1.f, 0.f, 0.f, 1.f);
#pragma unroll
        for (int k = 2; k >= 0; k--)
            if (warp > k) prefP = mm(prefP, wTotP[k]);

        float4 sufQ = make_float4(1.f, 0.f, 0.f, 1.f);
#pragma unroll
        for (int k = 1; k < 4; k++)
            if (warp < k) sufQ = mm(sufQ, wTotQ[k]);

        float4 exP = shflup4(sp, 1);
        if (lane == 0) exP = make_float4(1.f, 0.f, 0.f, 1.f);
        exP = mm(exP, prefP);
        fB[t] = make_float2(fmaxf(exP.x, exP.y), fmaxf(exP.z, exP.w)); // fwd @ seg start

        float4 exQ = shfldn4(sq, 1);
        if (lane == 31) exQ = make_float4(1.f, 0.f, 0.f, 1.f);
        exQ = mm(exQ, sufQ);
        gB[t] = make_float2(fmaxf(exQ.x, exQ.y), fmaxf(exQ.z, exQ.w)); // bwd @ seg end
    } else {
        __syncthreads();   // pair with phase-A internal sync
    }
    __syncthreads();

    // ---- Phase B: all 1024 threads; thread t owns positions [4t, 4t+4) ----
    {
        const int s = t >> 3, c = t & 7;
        const int idx = (s << 3) | (c ^ (s & 7));
        const float4 PPg = ppB[idx];
        const float4 SSg = ssB[idx];
        const float2 fs  = fB[s];
        const float2 gs  = gB[s];

        // forward msg at chunk start
        float f0 = fmaxf(PPg.x * fs.x, PPg.y * fs.y);
        float f1 = fmaxf(PPg.z * fs.x, PPg.w * fs.y);
        // backward msg at chunk end
        float bb0[4], bb1[4];
        bb0[3] = fmaxf(SSg.x * gs.x, SSg.y * gs.y);
        bb1[3] = fmaxf(SSg.z * gs.x, SSg.w * gs.y);
#pragma unroll
        for (int u = 2; u >= 0; u--) {
            int   o  = (nib >> (u + 1)) & 1;
            float p0 = o ? pt.pB0 : pt.pA0;
            float p1 = o ? pt.pB1 : pt.pA1;
            float y0 = p0 * bb0[u + 1];
            float y1 = p1 * bb1[u + 1];
            bb0[u] = fmaxf(y0 * pt.pd, y1 * pt.po);
            bb1[u] = fmaxf(y0 * pt.po, y1 * pt.pd);
        }

        float v0[4], v1[4];
#pragma unroll
        for (int u = 0; u < 4; u++) {
            int   o  = (nib >> u) & 1;
            float p0 = o ? pt.pB0 : pt.pA0;
            float p1 = o ? pt.pB1 : pt.pA1;
            float x0 = p0 * f0, x1 = p1 * f1;
            v0[u] = x0 * bb0[u];
            v1[u] = x1 * bb1[u];
            f0 = fmaxf(x0 * pt.pd, x1 * pt.po);
            f1 = fmaxf(x0 * pt.po, x1 * pt.pd);
        }

        // direct, fully-coalesced global stores: out[b][k][4t..4t+4)
        float4* out4 = reinterpret_cast<float4*>(out) + (size_t)b * 2048;
        out4[t]        = make_float4(v0[0], v0[1], v0[2], v0[3]);
        out4[1024 + t] = make_float4(v1[0], v1[1], v1[2], v1[3]);
    }
}

// ---------------------------------------------------------------------------
extern "C" void kernel_launch(void* const* d_in, const int* in_sizes, int n_in,
                              void* d_out, int out_size)
{
    const float* jp  = nullptr;
    const float* bp  = nullptr;
    const int*   obs = nullptr;
    for (int i = 0; i < n_in; i++) {
        if (in_sizes[i] == 1)      jp  = (const float*)d_in[i];
        else if (in_sizes[i] == 2) bp  = (const float*)d_in[i];
        else                       obs = (const int*)d_in[i];
    }
    float* out = (float*)d_out;

    fused<<<BATCH, NTHR>>>(jp, bp, obs, out);
}

// round 16
// speedup vs baseline: 1.2813x; 1.2813x over previous
#include <cuda_runtime.h>
#include <cstddef>

#define LCH   4096
#define BATCH 4096
#define SEG   32
#define NSEG  128

struct Pots { float pd, po, pA0, pA1, pB0, pB1; };

__device__ __forceinline__ Pots make_pots(const float* jp, const float* bp) {
    Pots P;
    float j = jp[0], b0 = bp[0], b1 = bp[1];
    P.pd  = expf( 0.25f * j);
    P.po  = expf(-0.25f * j);
    P.pA0 = expf(-0.5f * b0);  P.pA1 = expf(0.5f * b0);
    P.pB0 = expf(-0.5f * b1);  P.pB1 = expf(0.5f * b1);
    return P;
}

// (max,*) 2x2 matrix product: C = A x B.  layout x=m00 y=m01 z=m10 w=m11
__device__ __forceinline__ float4 mm(float4 A, float4 B) {
    return make_float4(
        fmaxf(A.x * B.x, A.y * B.z), fmaxf(A.x * B.y, A.y * B.w),
        fmaxf(A.z * B.x, A.w * B.z), fmaxf(A.z * B.y, A.w * B.w));
}

__device__ __forceinline__ float4 shflup4(float4 v, int d) {
    v.x = __shfl_up_sync(0xffffffffu, v.x, d);
    v.y = __shfl_up_sync(0xffffffffu, v.y, d);
    v.z = __shfl_up_sync(0xffffffffu, v.z, d);
    v.w = __shfl_up_sync(0xffffffffu, v.w, d);
    return v;
}
__device__ __forceinline__ float4 shfldn4(float4 v, int d) {
    v.x = __shfl_down_sync(0xffffffffu, v.x, d);
    v.y = __shfl_down_sync(0xffffffffu, v.y, d);
    v.z = __shfl_down_sync(0xffffffffu, v.z, d);
    v.w = __shfl_down_sync(0xffffffffu, v.w, d);
    return v;
}

// ---------------------------------------------------------------------------
// R12 structure with the staging tile halved to 16 KB via a two-pass
// sweep/store. Pass h covers chunks 4h..4h+3 of EVERY segment; the store
// scatters tile slots to their true row positions (8s + 4h + k).
// smem ~33.7 KB -> 6 blocks/SM at <=85 regs.
// ---------------------------------------------------------------------------
__global__ void __launch_bounds__(128, 6)
fused(const float* __restrict__ jp, const float* __restrict__ bp,
      const int* __restrict__ obs, float* __restrict__ out)
{
    __shared__ float4 ppB[1024];            // 16 KB chunk prefix products
    __shared__ float4 tile[1024];           // 16 KB half-row output stage
    __shared__ unsigned char smNib[1024];   // 1 KB obs nibbles
    __shared__ float4 lutP[16], lutQ[16];
    __shared__ float4 wTot[8];              // 0-3: P totals, 4-7: Q totals

    const int t = threadIdx.x, b = blockIdx.x;
    const int lane = t & 31, warp = t >> 5;

    const Pots pt = make_pots(jp, bp);

    // ---- obs -> nibbles (coalesced int4 loads) ----
    const int4* row4 = reinterpret_cast<const int4*>(obs + (size_t)b * LCH);
#pragma unroll
    for (int q = 0; q < 8; q++) {
        int  eq = q * 128 + t;
        int4 v  = row4[eq];
        smNib[eq] = (unsigned char)((v.x & 1) | ((v.y & 1) << 1) |
                                    ((v.z & 1) << 2) | ((v.w & 1) << 3));
    }

    // ---- 4-bit LUTs of 4-step transfer matrices ----
    if (t < 16) {
        float p00 = 1.f, p01 = 0.f, p10 = 0.f, p11 = 1.f;
        float q00 = 1.f, q01 = 0.f, q10 = 0.f, q11 = 1.f;
#pragma unroll
        for (int i = 0; i < 4; i++) {
            int   o  = (t >> i) & 1;
            float f0 = o ? pt.pB0 : pt.pA0;
            float f1 = o ? pt.pB1 : pt.pA1;
            float x0 = f0 * p00, x1 = f1 * p10, y0 = f0 * p01, y1 = f1 * p11;
            p00 = fmaxf(x0 * pt.pd, x1 * pt.po); p10 = fmaxf(x0 * pt.po, x1 * pt.pd);
            p01 = fmaxf(y0 * pt.pd, y1 * pt.po); p11 = fmaxf(y0 * pt.po, y1 * pt.pd);
            float a = f0 * fmaxf(q00 * pt.pd, q01 * pt.po);
            float c = f1 * fmaxf(q00 * pt.po, q01 * pt.pd);
            float d = f0 * fmaxf(q10 * pt.pd, q11 * pt.po);
            float e = f1 * fmaxf(q10 * pt.po, q11 * pt.pd);
            q00 = a; q01 = c; q10 = d; q11 = e;
        }
        lutP[t] = make_float4(p00, p01, p10, p11);
        lutQ[t] = make_float4(q00, q01, q10, q11);
    }
    __syncthreads();

    // ---- assemble 32-bit mask for segment t ----
    uint2 nb = reinterpret_cast<const uint2*>(smNib)[t];
    unsigned lo   = nb.x | (nb.x >> 4);
    unsigned lo16 = (lo & 0xFFu) | ((lo >> 8) & 0xFF00u);
    unsigned hi   = nb.y | (nb.y >> 4);
    unsigned hi16 = (hi & 0xFFu) | ((hi >> 8) & 0xFF00u);
    const unsigned bits = lo16 | (hi16 << 16);

    // ---- P compose with prefix products PP[g] -> smem (same-thread use) ----
    float4 P = make_float4(1.f, 0.f, 0.f, 1.f);
#pragma unroll
    for (int c = 0; c < 8; c++) {
        ppB[c * 128 + t] = P;            // PP[c] = chunk_{c-1} o ... o chunk_0
        P = mm(lutP[(bits >> (4 * c)) & 15u], P);
    }

    // ---- Q compose with suffix products SS[g] in registers ----
    float4 SS[8];                 // SS[g] = chunkQ_{g+1} . ... . chunkQ_7 ; SS[7]=I
    float4 Q = make_float4(1.f, 0.f, 0.f, 1.f);
#pragma unroll
    for (int c = 7; c >= 0; c--) {
        SS[c] = Q;
        Q = mm(lutQ[(bits >> (4 * c)) & 15u], Q);
    }

    // ---- block scan: forward prefix of P, backward suffix of Q ----
    float4 sp = P;
#pragma unroll
    for (int d = 1; d < 32; d <<= 1) {
        float4 o = shflup4(sp, d);
        if (lane >= d) sp = mm(sp, o);
    }
    if (lane == 31) wTot[warp] = sp;

    float4 sq = Q;
#pragma unroll
    for (int d = 1; d < 32; d <<= 1) {
        float4 o = shfldn4(sq, d);
        if (lane + d < 32) sq = mm(sq, o);
    }
    if (lane == 0) wTot[4 + warp] = sq;
    __syncthreads();

    float4 prefP = make_float4(1.f, 0.f, 0.f, 1.f);
#pragma unroll
    for (int k = 2; k >= 0; k--)
        if (warp > k) prefP = mm(prefP, wTot[k]);

    float4 sufQ = make_float4(1.f, 0.f, 0.f, 1.f);
#pragma unroll
    for (int k = 1; k < 4; k++)
        if (warp < k) sufQ = mm(sufQ, wTot[4 + k]);

    float4 exP = shflup4(sp, 1);
    if (lane == 0) exP = make_float4(1.f, 0.f, 0.f, 1.f);
    exP = mm(exP, prefP);
    const float fs0 = fmaxf(exP.x, exP.y), fs1 = fmaxf(exP.z, exP.w); // fwd @ seg start

    float4 exQ = shfldn4(sq, 1);
    if (lane == 31) exQ = make_float4(1.f, 0.f, 0.f, 1.f);
    exQ = mm(exQ, sufQ);
    const float g0 = fmaxf(exQ.x, exQ.y), g1 = fmaxf(exQ.z, exQ.w);  // bwd @ seg end

    // ---- two-pass sweep + store: pass h = chunks 4h..4h+3 of every segment ----
    float4* out4 = reinterpret_cast<float4*>(out) + (size_t)b * 2048;
    const int xr = (t >> 1) & 3;     // writer swizzle (conflict-free, verified)

#pragma unroll
    for (int h = 0; h < 2; h++) {
#pragma unroll
        for (int k = 0; k < 4; k++) {
            const int gg = h * 4 + k;

            // forward msg at chunk start from smem prefix product
            float4 PPg = ppB[gg * 128 + t];
            float f0 = fmaxf(PPg.x * fs0, PPg.y * fs1);
            float f1 = fmaxf(PPg.z * fs0, PPg.w * fs1);

            // backward msgs within chunk from suffix product (3 local steps)
            float bb0[4], bb1[4];
            bb0[3] = fmaxf(SS[gg].x * g0, SS[gg].y * g1);
            bb1[3] = fmaxf(SS[gg].z * g0, SS[gg].w * g1);
#pragma unroll
            for (int u = 2; u >= 0; u--) {
                int   i  = gg * 4 + u;
                int   o  = (bits >> (i + 1)) & 1;
                float p0 = o ? pt.pB0 : pt.pA0;
                float p1 = o ? pt.pB1 : pt.pA1;
                float y0 = p0 * bb0[u + 1];
                float y1 = p1 * bb1[u + 1];
                bb0[u] = fmaxf(y0 * pt.pd, y1 * pt.po);
                bb1[u] = fmaxf(y0 * pt.po, y1 * pt.pd);
            }

            float v0[4], v1[4];
#pragma unroll
            for (int u = 0; u < 4; u++) {
                int   i  = gg * 4 + u;
                int   o  = (bits >> i) & 1;
                float p0 = o ? pt.pB0 : pt.pA0;
                float p1 = o ? pt.pB1 : pt.pA1;
                float x0 = p0 * f0, x1 = p1 * f1;
                v0[u] = x0 * bb0[u];
                v1[u] = x1 * bb1[u];
                f0 = fmaxf(x0 * pt.pd, x1 * pt.po);
                f1 = fmaxf(x0 * pt.po, x1 * pt.pd);
            }
            tile[((t * 4 + k) ^ xr)]       = make_float4(v0[0], v0[1], v0[2], v0[3]);
            tile[512 + ((t * 4 + k) ^ xr)] = make_float4(v1[0], v1[1], v1[2], v1[3]);
        }
        __syncthreads();

        // scatter-store this pass: tile slot (4s+k)^xr_s  ->  row float4 8s+4h+k
#pragma unroll
        for (int r = 0; r < 4; r++) {
            int idx  = r * 128 + t;                 // = 4s + k, idx in [0,512)
            int slot = idx ^ ((idx >> 3) & 3);      // matches writer swizzle
            int s    = idx >> 2;
            int k2   = idx & 3;
            int dst  = s * 8 + h * 4 + k2;          // true row position
            out4[dst]        = tile[slot];
            out4[1024 + dst] = tile[512 + slot];
        }
        if (h == 0) __syncthreads();               // protect tile reuse
    }
}

// ---------------------------------------------------------------------------
extern "C" void kernel_launch(void* const* d_in, const int* in_sizes, int n_in,
                              void* d_out, int out_size)
{
    const float* jp  = nullptr;
    const float* bp  = nullptr;
    const int*   obs = nullptr;
    for (int i = 0; i < n_in; i++) {
        if (in_sizes[i] == 1)      jp  = (const float*)d_in[i];
        else if (in_sizes[i] == 2) bp  = (const float*)d_in[i];
        else                       obs = (const int*)d_in[i];
    }
    float* out = (float*)d_out;

    fused<<<BATCH, 128>>>(jp, bp, obs, out);
}

// round 17
// speedup vs baseline: 1.3648x; 1.0652x over previous
#include <cuda_runtime.h>
#include <cstddef>

#define LCH   4096
#define BATCH 4096
#define SEG   32
#define NSEG  128

struct Pots { float pd, po, pA0, pA1, pB0, pB1; };

__device__ __forceinline__ Pots make_pots(const float* jp, const float* bp) {
    Pots P;
    float j = jp[0], b0 = bp[0], b1 = bp[1];
    P.pd  = expf( 0.25f * j);
    P.po  = expf(-0.25f * j);
    P.pA0 = expf(-0.5f * b0);  P.pA1 = expf(0.5f * b0);
    P.pB0 = expf(-0.5f * b1);  P.pB1 = expf(0.5f * b1);
    return P;
}

// (max,*) 2x2 matrix product: C = A x B.  layout x=m00 y=m01 z=m10 w=m11
__device__ __forceinline__ float4 mm(float4 A, float4 B) {
    return make_float4(
        fmaxf(A.x * B.x, A.y * B.z), fmaxf(A.x * B.y, A.y * B.w),
        fmaxf(A.z * B.x, A.w * B.z), fmaxf(A.z * B.y, A.w * B.w));
}

__device__ __forceinline__ float4 shflup4(float4 v, int d) {
    v.x = __shfl_up_sync(0xffffffffu, v.x, d);
    v.y = __shfl_up_sync(0xffffffffu, v.y, d);
    v.z = __shfl_up_sync(0xffffffffu, v.z, d);
    v.w = __shfl_up_sync(0xffffffffu, v.w, d);
    return v;
}
__device__ __forceinline__ float4 shfldn4(float4 v, int d) {
    v.x = __shfl_down_sync(0xffffffffu, v.x, d);
    v.y = __shfl_down_sync(0xffffffffu, v.y, d);
    v.z = __shfl_down_sync(0xffffffffu, v.z, d);
    v.w = __shfl_down_sync(0xffffffffu, v.w, d);
    return v;
}

// ---------------------------------------------------------------------------
// R9 structure with BALANCED 4+4 quartering: SSq[4] suffix products (bwd)
// and PPq[3] prefix products (fwd) make all 4 quarters of the segment
// independent in both directions at ~R9 register cost.
// ---------------------------------------------------------------------------
__global__ void __launch_bounds__(128, 4)
fused(const float* __restrict__ jp, const float* __restrict__ bp,
      const int* __restrict__ obs, float* __restrict__ out)
{
    const int t = threadIdx.x, b = blockIdx.x;
    const int lane = t & 31, warp = t >> 5;

    __shared__ unsigned char smNib[1024];
    __shared__ float4 lutP[16], lutQ[16];
    __shared__ float4 wTotP[4], wTotQ[4];
    __shared__ float  smo[2 * LCH];         // 32 KB output stage
    float4* sm4 = reinterpret_cast<float4*>(smo);

    const Pots pt = make_pots(jp, bp);

    // ---- obs -> nibbles (coalesced int4 loads) ----
    const int4* row4 = reinterpret_cast<const int4*>(obs + (size_t)b * LCH);
#pragma unroll
    for (int q = 0; q < 8; q++) {
        int  eq = q * 128 + t;
        int4 v  = row4[eq];
        smNib[eq] = (unsigned char)((v.x & 1) | ((v.y & 1) << 1) |
                                    ((v.z & 1) << 2) | ((v.w & 1) << 3));
    }

    // ---- 4-bit LUTs of 4-step transfer matrices ----
    if (t < 16) {
        float p00 = 1.f, p01 = 0.f, p10 = 0.f, p11 = 1.f;
        float q00 = 1.f, q01 = 0.f, q10 = 0.f, q11 = 1.f;
#pragma unroll
        for (int i = 0; i < 4; i++) {
            int   o  = (t >> i) & 1;
            float f0 = o ? pt.pB0 : pt.pA0;
            float f1 = o ? pt.pB1 : pt.pA1;
            float x0 = f0 * p00, x1 = f1 * p10, y0 = f0 * p01, y1 = f1 * p11;
            p00 = fmaxf(x0 * pt.pd, x1 * pt.po); p10 = fmaxf(x0 * pt.po, x1 * pt.pd);
            p01 = fmaxf(y0 * pt.pd, y1 * pt.po); p11 = fmaxf(y0 * pt.po, y1 * pt.pd);
            float a = f0 * fmaxf(q00 * pt.pd, q01 * pt.po);
            float c = f1 * fmaxf(q00 * pt.po, q01 * pt.pd);
            float d = f0 * fmaxf(q10 * pt.pd, q11 * pt.po);
            float e = f1 * fmaxf(q10 * pt.po, q11 * pt.pd);
            q00 = a; q01 = c; q10 = d; q11 = e;
        }
        lutP[t] = make_float4(p00, p01, p10, p11);
        lutQ[t] = make_float4(q00, q01, q10, q11);
    }
    __syncthreads();

    // ---- assemble 32-bit mask for segment t ----
    uint2 nb = reinterpret_cast<const uint2*>(smNib)[t];
    unsigned lo   = nb.x | (nb.x >> 4);
    unsigned lo16 = (lo & 0xFFu) | ((lo >> 8) & 0xFF00u);
    unsigned hi   = nb.y | (nb.y >> 4);
    unsigned hi16 = (hi & 0xFFu) | ((hi >> 8) & 0xFF00u);
    const unsigned bits = lo16 | (hi16 << 16);

    // ---- P compose, saving quarter prefix products PPq[q-1]=chunks 0..2q-1 ----
    float4 PPq[3];
    float4 P = lutP[bits & 15];
#pragma unroll
    for (int c = 1; c < 8; c++) {
        if (c == 2) PPq[0] = P;          // chunks 0..1  (positions 0..7)
        if (c == 4) PPq[1] = P;          // chunks 0..3  (positions 0..15)
        if (c == 6) PPq[2] = P;          // chunks 0..5  (positions 0..23)
        P = mm(lutP[(bits >> (4 * c)) & 15u], P);
    }
    // P = full segment forward matrix

    // ---- Q compose, saving quarter suffix products SSq[q]=chunks 2q+2..7 ----
    float4 SSq[4];
    float4 Q = make_float4(1.f, 0.f, 0.f, 1.f);
#pragma unroll
    for (int c = 7; c >= 0; c--) {
        if (c == 7) SSq[3] = Q;          // I
        if (c == 5) SSq[2] = Q;          // chunks 6..7
        if (c == 3) SSq[1] = Q;          // chunks 4..7
        if (c == 1) SSq[0] = Q;          // chunks 2..7
        Q = mm(lutQ[(bits >> (4 * c)) & 15u], Q);
    }
    // Q = full segment backward matrix

    // ---- block scan: forward prefix of P, backward suffix of Q ----
    float4 sp = P;
#pragma unroll
    for (int d = 1; d < 32; d <<= 1) {
        float4 o = shflup4(sp, d);
        if (lane >= d) sp = mm(sp, o);
    }
    if (lane == 31) wTotP[warp] = sp;

    float4 sq = Q;
#pragma unroll
    for (int d = 1; d < 32; d <<= 1) {
        float4 o = shfldn4(sq, d);
        if (lane + d < 32) sq = mm(sq, o);
    }
    if (lane == 0) wTotQ[warp] = sq;
    __syncthreads();

    float4 prefP = make_float4(1.f, 0.f, 0.f, 1.f);
#pragma unroll
    for (int k = 2; k >= 0; k--)
        if (warp > k) prefP = mm(prefP, wTotP[k]);

    float4 sufQ = make_float4(1.f, 0.f, 0.f, 1.f);
#pragma unroll
    for (int k = 1; k < 4; k++)
        if (warp < k) sufQ = mm(sufQ, wTotQ[k]);

    float4 exP = shflup4(sp, 1);
    if (lane == 0) exP = make_float4(1.f, 0.f, 0.f, 1.f);
    exP = mm(exP, prefP);
    const float fs0 = fmaxf(exP.x, exP.y), fs1 = fmaxf(exP.z, exP.w); // fwd @ seg start

    float4 exQ = shfldn4(sq, 1);
    if (lane == 31) exQ = make_float4(1.f, 0.f, 0.f, 1.f);
    exQ = mm(exQ, sufQ);
    const float g0 = fmaxf(exQ.x, exQ.y), g1 = fmaxf(exQ.z, exQ.w);  // bwd @ seg end

    // ---- fused sweep: 4 independent quarters of 8 positions each ----
    const int xr = t & 7;
#pragma unroll
    for (int q = 0; q < 4; q++) {
        // forward msg at quarter start
        float f0, f1;
        if (q == 0) { f0 = fs0; f1 = fs1; }
        else {
            float4 PPg = PPq[q - 1];
            f0 = fmaxf(PPg.x * fs0, PPg.y * fs1);
            f1 = fmaxf(PPg.z * fs0, PPg.w * fs1);
        }

        // backward msgs within quarter (7 local steps from suffix product)
        float bb0[8], bb1[8];
        bb0[7] = fmaxf(SSq[q].x * g0, SSq[q].y * g1);
        bb1[7] = fmaxf(SSq[q].z * g0, SSq[q].w * g1);
#pragma unroll
        for (int u = 6; u >= 0; u--) {
            int   i  = q * 8 + u;
            int   o  = (bits >> (i + 1)) & 1;
            float p0 = o ? pt.pB0 : pt.pA0;
            float p1 = o ? pt.pB1 : pt.pA1;
            float y0 = p0 * bb0[u + 1];
            float y1 = p1 * bb1[u + 1];
            bb0[u] = fmaxf(y0 * pt.pd, y1 * pt.po);
            bb1[u] = fmaxf(y0 * pt.po, y1 * pt.pd);
        }

        // beliefs, two float4 groups per quarter
#pragma unroll
        for (int hg = 0; hg < 2; hg++) {
            float v0[4], v1[4];
#pragma unroll
            for (int u2 = 0; u2 < 4; u2++) {
                int   u  = hg * 4 + u2;
                int   i  = q * 8 + u;
                int   o  = (bits >> i) & 1;
                float p0 = o ? pt.pB0 : pt.pA0;
                float p1 = o ? pt.pB1 : pt.pA1;
                float x0 = p0 * f0, x1 = p1 * f1;
                v0[u2] = x0 * bb0[u];
                v1[u2] = x1 * bb1[u];
                f0 = fmaxf(x0 * pt.pd, x1 * pt.po);
                f1 = fmaxf(x0 * pt.po, x1 * pt.pd);
            }
            int gg = q * 2 + hg;
            sm4[(t * 8 + gg) ^ xr]        = make_float4(v0[0], v0[1], v0[2], v0[3]);
            sm4[(1024 + t * 8 + gg) ^ xr] = make_float4(v1[0], v1[1], v1[2], v1[3]);
        }
    }
    __syncthreads();

    // ---- single LDS pass + fully-coalesced store: out[b][k][t] ----
    float4* out4 = reinterpret_cast<float4*>(out) + (size_t)b * 2048;
#pragma unroll
    for (int r = 0; r < 16; r++) {
        int w4 = r * 128 + t;
        int x  = (w4 >> 3) & 7;
        out4[w4] = sm4[w4 ^ x];
    }
}

// ---------------------------------------------------------------------------
extern "C" void kernel_launch(void* const* d_in, const int* in_sizes, int n_in,
                              void* d_out, int out_size)
{
    const float* jp  = nullptr;
    const float* bp  = nullptr;
    const int*   obs = nullptr;
    for (int i = 0; i < n_in; i++) {
        if (in_sizes[i] == 1)      jp  = (const float*)d_in[i];
        else if (in_sizes[i] == 2) bp  = (const float*)d_in[i];
        else                       obs = (const int*)d_in[i];
    }
    float* out = (float*)d_out;

    fused<<<BATCH, 128>>>(jp, bp, obs, out);
}